// round 5
// baseline (speedup 1.0000x reference)
#include <cuda_runtime.h>
#include <cstdint>

// HighOrderFactorizationMachineModel: BATCH=16384, F=20 fields (dim 50000 each),
// EMBED_DIM=16, ORDER=3. emb row = 32 floats: [0:16) order-2, [16:32) order-3.
// Closed forms: e2=(p1^2-p2)/2, e3=(p1^3-3p1p2+2p3)/6.
//
// R5: gathers go through cp.async.cg (LDGSTS, L1-bypass) into shared memory.
// R1-R4 were invariant at ~10.7us across MLP 4..20 and occ 53..85% -> the cap
// is SM-level outstanding-miss buffering, not warp-level ILP. cp.async.cg uses
// the smem-fill path (no L1 line allocation, no register scoreboard) with no
// observed pipeline depth cap. 8 lanes x 16B cover one 128B row; each lane
// issues 5 cp.asyncs (rows lane>>3, +4, +8, +12, +16).

#define FM_BATCH 16384
#define FM_F 20
#define FM_FIELD_DIM 50000
#define WARPS_PER_BLOCK 8
#define ROW_FLOATS 32

__global__ __launch_bounds__(32 * WARPS_PER_BLOCK)
void fm_ho_kernel(const int* __restrict__ x,
                  const float* __restrict__ emb,
                  const float* __restrict__ lin,
                  const float* __restrict__ bias,
                  float* __restrict__ out)
{
    __shared__ float buf[WARPS_PER_BLOCK][FM_F * ROW_FLOATS];  // 2560 B/warp

    const int wid  = threadIdx.x >> 5;
    const int lane = threadIdx.x & 31;
    const int s = blockIdx.x * WARPS_PER_BLOCK + wid;  // one sample per warp

    // Index row: 20 ints = 80 B, 16B-aligned -> 5x int4 broadcast loads.
    int idx[FM_F];
    {
        const int4* xr = (const int4*)(x + s * FM_F);
        #pragma unroll
        for (int q = 0; q < FM_F / 4; q++) {
            const int4 t = __ldg(&xr[q]);
            idx[4 * q + 0] = t.x + (4 * q + 0) * FM_FIELD_DIM;
            idx[4 * q + 1] = t.y + (4 * q + 1) * FM_FIELD_DIM;
            idx[4 * q + 2] = t.z + (4 * q + 2) * FM_FIELD_DIM;
            idx[4 * q + 3] = t.w + (4 * q + 3) * FM_FIELD_DIM;
        }
    }

    // Stage 20 rows into smem via cp.async.cg. Lane covers chunk (lane&7) of
    // rows (lane>>3) + 4i, i = 0..4. 16B per op, both sides 16B-aligned.
    {
        const int chunk = (lane & 7) * 4;          // float offset within row
        const int rbase = lane >> 3;               // 0..3
        uint32_t smem_base;
        asm("{ .reg .u64 t; cvta.to.shared.u64 t, %1; cvt.u32.u64 %0, t; }"
            : "=r"(smem_base) : "l"(&buf[wid][0]));
        #pragma unroll
        for (int i = 0; i < 5; i++) {
            const int r = rbase + 4 * i;
            const float* g = emb + (long)idx[r] * ROW_FLOATS + chunk;
            const uint32_t sdst = smem_base + (r * ROW_FLOATS + chunk) * 4;
            asm volatile("cp.async.cg.shared.global [%0], [%1], 16;"
                         :: "r"(sdst), "l"(g));
        }
        asm volatile("cp.async.commit_group;");
    }

    // Overlap: linear-term gather on lanes 0..19 while cp.asyncs are in flight.
    float linv = 0.0f;
    if (lane < FM_F)
        linv = __ldg(&lin[idx[lane]]);

    asm volatile("cp.async.wait_group 0;" ::: "memory");
    __syncwarp();

    // Power sums: lane l reads element l of each row (bank l every time ->
    // conflict-free, row stride = 128 B = 32 banks).
    float p1 = 0.0f, p2 = 0.0f, p3 = 0.0f;
    #pragma unroll
    for (int f = 0; f < FM_F; f++) {
        const float w = buf[wid][f * ROW_FLOATS + lane];
        const float w2 = w * w;
        p1 += w;
        p2 += w2;
        p3 += w2 * w;
    }

    // Lanes 0..15: order-2 dims. Lanes 16..31: order-3 dims.
    float term;
    if (lane < 16) {
        term = 0.5f * (p1 * p1 - p2);
    } else {
        term = (p1 * p1 * p1 - 3.0f * p1 * p2 + 2.0f * p3) * (1.0f / 6.0f);
    }
    term += linv;   // lanes 0..19 contribute linear part, others add 0

    // Warp-wide sum.
    #pragma unroll
    for (int o = 16; o > 0; o >>= 1)
        term += __shfl_xor_sync(0xffffffffu, term, o);

    if (lane == 0)
        out[s] = term + __ldg(&bias[0]);
}

extern "C" void kernel_launch(void* const* d_in, const int* in_sizes, int n_in,
                              void* d_out, int out_size)
{
    const int*   x    = (const int*)d_in[0];
    const float* emb  = (const float*)d_in[1];
    const float* lin  = (const float*)d_in[2];
    const float* bias = (const float*)d_in[3];
    float*       out  = (float*)d_out;

    const int threads = 32 * WARPS_PER_BLOCK;
    const int blocks  = FM_BATCH / WARPS_PER_BLOCK;
    fm_ho_kernel<<<blocks, threads>>>(x, emb, lin, bias, out);
}

// round 6
// speedup vs baseline: 1.3623x; 1.3623x over previous
#include <cuda_runtime.h>
#include <cstdint>

// HighOrderFactorizationMachineModel: BATCH=16384, F=20, EMBED_DIM=16, ORDER=3.
// emb row = 32 floats: [0:16) order-2 dims, [16:32) order-3 dims.
// Closed forms: e2=(p1^2-p2)/2 ; e3=(p1^3-3p1p2+2p3)/6  (per dim).
//
// R6: 8 lanes per sample, 4 samples per warp, every emb gather an LDG.128.
//  - 4096 warps total -> ~single resident wave on 148 SMs (no wave tail).
//  - 20 LDG.128/warp instead of 80 LDG.32 (same lines, 1/4 instructions).
//  - lane k of a sample's 8-lane group owns dims 4k..4k+3 (float4).

#define FM_BATCH 16384
#define FM_F 20
#define FM_FIELD_DIM 50000

__global__ __launch_bounds__(256)
void fm_ho_kernel(const int* __restrict__ x,
                  const float* __restrict__ emb,
                  const float* __restrict__ lin,
                  const float* __restrict__ bias,
                  float* __restrict__ out)
{
    const int warp = (blockIdx.x * blockDim.x + threadIdx.x) >> 5;
    const int lane = threadIdx.x & 31;
    const int g    = lane >> 3;          // sample group 0..3 within warp
    const int k    = lane & 7;           // dim-quad 0..7 within sample
    const int s    = warp * 4 + g;       // this lane's sample

    // All 8 lanes of a group load the group's full index row (5x int4
    // broadcast; 4 distinct 80B rows per warp, contiguous -> ~3 lines).
    int idx[FM_F];
    {
        const int4* xr = (const int4*)(x + s * FM_F);
        #pragma unroll
        for (int q = 0; q < FM_F / 4; q++) {
            const int4 t = __ldg(&xr[q]);
            idx[4 * q + 0] = t.x + (4 * q + 0) * FM_FIELD_DIM;
            idx[4 * q + 1] = t.y + (4 * q + 1) * FM_FIELD_DIM;
            idx[4 * q + 2] = t.z + (4 * q + 2) * FM_FIELD_DIM;
            idx[4 * q + 3] = t.w + (4 * q + 3) * FM_FIELD_DIM;
        }
    }

    // Per-dim power sums for this lane's 4 dims (d = 4k + c).
    float p1[4] = {0.f, 0.f, 0.f, 0.f};
    float p2[4] = {0.f, 0.f, 0.f, 0.f};
    float p3[4] = {0.f, 0.f, 0.f, 0.f};

    // Gathers in two batches of 10 LDG.128 (40 lines in flight per warp).
    #pragma unroll
    for (int half = 0; half < 2; half++) {
        float4 v[10];
        #pragma unroll
        for (int j = 0; j < 10; j++) {
            const int f = half * 10 + j;
            v[j] = __ldg((const float4*)(emb + (long)idx[f] * 32) + k);
        }
        #pragma unroll
        for (int j = 0; j < 10; j++) {
            const float w0 = v[j].x, w1 = v[j].y, w2 = v[j].z, w3 = v[j].w;
            p1[0] += w0;           p1[1] += w1;           p1[2] += w2;           p1[3] += w3;
            p2[0] += w0 * w0;      p2[1] += w1 * w1;      p2[2] += w2 * w2;      p2[3] += w3 * w3;
            p3[0] += w0 * w0 * w0; p3[1] += w1 * w1 * w1; p3[2] += w2 * w2 * w2; p3[3] += w3 * w3 * w3;
        }
    }

    // Per-dim interaction terms. k<4 -> dims 0..15 (order-2); k>=4 -> 16..31.
    float term = 0.0f;
    if (k < 4) {
        #pragma unroll
        for (int c = 0; c < 4; c++)
            term += 0.5f * (p1[c] * p1[c] - p2[c]);
    } else {
        #pragma unroll
        for (int c = 0; c < 4; c++)
            term += (p1[c] * p1[c] * p1[c] - 3.0f * p1[c] * p2[c] + 2.0f * p3[c])
                    * (1.0f / 6.0f);
    }

    // Linear part: lanes k=0..7 cover fields k, k+8, and (k<4) k+16.
    term += __ldg(&lin[idx[k]]);
    term += __ldg(&lin[idx[k + 8]]);
    if (k < 4) term += __ldg(&lin[idx[k + 16]]);

    // Reduce across the 8 lanes of this sample's group (xor 1,2,4 stay in-group).
    #pragma unroll
    for (int o = 1; o < 8; o <<= 1)
        term += __shfl_xor_sync(0xffffffffu, term, o);

    if (k == 0)
        out[s] = term + __ldg(&bias[0]);
}

extern "C" void kernel_launch(void* const* d_in, const int* in_sizes, int n_in,
                              void* d_out, int out_size)
{
    const int*   x    = (const int*)d_in[0];
    const float* emb  = (const float*)d_in[1];
    const float* lin  = (const float*)d_in[2];
    const float* bias = (const float*)d_in[3];
    float*       out  = (float*)d_out;

    // 16384 samples, 4 per warp, 8 warps/block -> 512 blocks (~1 wave).
    const int threads = 256;
    const int blocks  = FM_BATCH / (4 * (threads / 32));
    fm_ho_kernel<<<blocks, threads>>>(x, emb, lin, bias, out);
}